// round 3
// baseline (speedup 1.0000x reference)
#include <cuda_runtime.h>
#include <cstdint>

// Problem dims (fixed by the dataset's setup_inputs)
#define C_   128
#define H_   56
#define W_   56
#define HW_  3136
#define TOTAL_ (16 * 128 * 3136)

#define TPB   224          // 56 cols x 4 vertical strips
#define RPB   28           // rows per block (2 blocks cover H=56)

// set.ge -> -1 (true) / 0 (false): single SASS FSET, no SEL needed
__device__ __forceinline__ int setge(float a, float b) {
    int r;
    asm("set.ge.s32.f32 %0, %1, %2;" : "=r"(r) : "f"(a), "f"(b));
    return r;
}

__global__ __launch_bounds__(TPB)
void rrsvm_kernel(const float* __restrict__ x,
                  const float* __restrict__ s,
                  float* __restrict__ vout,
                  float* __restrict__ idxout)
{
    __shared__ float ssm[9];
    __shared__ __align__(16) float stage[2][TPB * 9];   // double-buffered idx stage

    const int tid  = threadIdx.x;
    const int bc   = blockIdx.x >> 1;          // (b*C + c)
    const int R0   = (blockIdx.x & 1) * RPB;   // slab row base
    const int xcol = tid % 56;
    const int sidx = tid / 56;                 // strip 0..3
    const int y0   = R0 + sidx * 7;            // first output row of this strip

    if (tid < 9) ssm[tid] = __ldg(s + (bc & (C_ - 1)) * 9 + tid);
    __syncthreads();

    const float* __restrict__ xb = x + (size_t)bc * HW_ + xcol;
    const bool pxl = (xcol > 0);
    const bool pxr = (xcol < W_ - 1);

    float v[3][3];      // rolling rows (slot-indexed)
    int   Wm[3][3];     // within-row masks per slot: pairs (0,1),(0,2),(1,2)
    int   CX[2][9];     // cross-row masks, parity buffered: top-mid for current iter

#define LOADROW(slot, gr)                                               \
    {                                                                   \
        const bool rok = ((unsigned)(gr) < (unsigned)H_);               \
        const float* p = xb + (gr) * W_;                                \
        v[slot][0] = (rok & pxl) ? __ldg(p - 1) : 0.f;                  \
        v[slot][1] = rok ? __ldg(p) : 0.f;                              \
        v[slot][2] = (rok & pxr) ? __ldg(p + 1) : 0.f;                  \
    }
#define WITHIN(slot)                                                    \
    {                                                                   \
        Wm[slot][0] = setge(v[slot][0], v[slot][1]);                    \
        Wm[slot][1] = setge(v[slot][0], v[slot][2]);                    \
        Wm[slot][2] = setge(v[slot][1], v[slot][2]);                    \
    }

    // prologue: rows y0-1, y0 into slots 0,1 (+ their masks)
    LOADROW(0, y0 - 1);
    LOADROW(1, y0);
    WITHIN(0);
    WITHIN(1);
#pragma unroll
    for (int a = 0; a < 3; a++)
#pragma unroll
        for (int b = 0; b < 3; b++)
            CX[0][a * 3 + b] = setge(v[0][a], v[1][b]);

    const int    stbase = sidx * 504 + xcol * 9;
    const size_t obase  = (size_t)bc * HW_;

#pragma unroll
    for (int r = 0; r < 7; r++) {
        const int top = r % 3, mid = (r + 1) % 3, bot = (r + 2) % 3;
        const int p   = r & 1;

        LOADROW(bot, y0 + r + 1);
        WITHIN(bot);

        // new cross masks: top-bot (temp) and mid-bot (written straight into
        // next iteration's carry slot CX[1-p], which becomes top-mid then)
        int nx_tb[9];
#pragma unroll
        for (int a = 0; a < 3; a++)
#pragma unroll
            for (int b = 0; b < 3; b++) {
                nx_tb[a * 3 + b]    = setge(v[top][a], v[bot][b]);
                CX[1 - p][a * 3 + b] = setge(v[mid][a], v[bot][b]);
            }

        // stable-descending ranks from signed masks (-1/0)
        int rank[9];
#pragma unroll
        for (int e = 0; e < 9; e++) rank[e] = 8 - e;
#pragma unroll
        for (int e = 0; e < 9; e++) {
#pragma unroll
            for (int f = e + 1; f < 9; f++) {
                const int re = e / 3, ce = e % 3;
                const int rf = f / 3, cf = f % 3;
                int m;
                if (re == rf) {
                    const int sl = (re == 0) ? top : (re == 1 ? mid : bot);
                    const int pi = (ce == 0) ? (cf == 1 ? 0 : 1) : 2;
                    m = Wm[sl][pi];
                } else if (re == 0 && rf == 1) {
                    m = CX[p][ce * 3 + cf];
                } else if (re == 0) {
                    m = nx_tb[ce * 3 + cf];
                } else {
                    m = CX[1 - p][ce * 3 + cf];   // mid-bot
                }
                rank[e] += m;   // m = -1 when e beats f
                rank[f] -= m;
            }
        }

        // value accumulate + index scatter into this iteration's stage buffer
        float  acc = 0.f;
        float* st  = stage[p] + stbase;
#pragma unroll
        for (int e = 0; e < 9; e++) {
            const int sl = (e < 3) ? top : (e < 6 ? mid : bot);
            acc = fmaf(v[sl][e % 3], ssm[rank[e]], acc);
            st[rank[e]] = (float)e;     // constant payload, no I2F
        }

        if (vout)
            vout[obase + (size_t)(y0 + r) * W_ + xcol] = acc;

        __syncthreads();

        if (idxout) {
            // 2016 staged floats = 504 float4, in 4 contiguous 126-float4 runs
            // (one per strip: output rows R0 + 7*run + r)
            const float4* sf = (const float4*)stage[p];
#pragma unroll
            for (int k = 0; k < 3; k++) {
                const int i = tid + k * TPB;
                if (k < 2 || tid < 504 - 2 * TPB) {
                    const int run  = i / 126;
                    const int j    = i - run * 126;
                    const int grow = R0 + run * 7 + r;
                    ((float4*)(idxout + (obase + (size_t)grow * W_) * 9))[j] = sf[i];
                }
            }
        }
    }
}

extern "C" void kernel_launch(void* const* d_in, const int* in_sizes, int n_in,
                              void* d_out, int out_size) {
    const float* x = (const float*)d_in[0];
    const float* s = (const float*)d_in[1];

    float* vout   = (float*)d_out;
    float* idxout = nullptr;

    if (out_size >= 10 * TOTAL_) {
        idxout = (float*)d_out + TOTAL_;   // [out | indices] concatenated
    } else if (out_size == 9 * TOTAL_) {
        idxout = (float*)d_out;            // indices only
        vout   = nullptr;
    }

    const int blocks = 16 * 128 * 2;       // 2 row-slabs per (b,c)
    rrsvm_kernel<<<blocks, TPB>>>(x, s, vout, idxout);
}

// round 4
// speedup vs baseline: 3.2789x; 3.2789x over previous
#include <cuda_runtime.h>
#include <cstdint>

// Problem dims (fixed by the dataset's setup_inputs)
#define C_   128
#define H_   56
#define W_   56
#define HW_  3136
#define TOTAL_ (16 * 128 * 3136)

#define NPAIR_BC  1568                    // HW/2 pixel-pairs per (b,c)
#define NPAIR_TOT (16 * 128 * NPAIR_BC)   // 3,211,264
#define TPB 256

// set.ge -> -1 (true) / 0 (false): single SASS FSET, no predication
__device__ __forceinline__ int setge(float a, float b) {
    int r;
    asm("set.ge.s32.f32 %0, %1, %2;" : "=r"(r) : "f"(a), "f"(b));
    return r;
}

__global__ __launch_bounds__(TPB)
void rrsvm_kernel(const float* __restrict__ x,
                  const float* __restrict__ s,
                  float* __restrict__ vout,
                  float* __restrict__ idxout)
{
    __shared__ float ssm[8][9];                       // per-warp rank weights
    __shared__ __align__(16) float stage[8][576];     // per-warp idx staging

    const int tid  = threadIdx.x;
    const int warp = tid >> 5;
    const int lane = tid & 31;
    const int t    = blockIdx.x * TPB + tid;          // pair id, exact grid

    const int bc = t / NPAIR_BC;                      // b*C + c
    const int q  = t - bc * NPAIR_BC;
    const int y  = q / 28;                            // output row
    const int xx = (q - y * 28) * 2;                  // left pixel col (even)

    // warp never straddles (b,c): NPAIR_BC = 1568 is a multiple of 32
    if (lane < 9)
        ssm[warp][lane] = __ldg(s + (bc & (C_ - 1)) * 9 + lane);
    __syncwarp();

    const float* __restrict__ xb = x + (size_t)bc * HW_;
    const bool pl = (xx > 0);          // col xx-1 valid
    const bool pr = (xx < W_ - 2);     // col xx+2 valid

    // 3 rows x 4 cols covering both 3x3 windows (zero padding = real values)
    float v[3][4];
#pragma unroll
    for (int rr = 0; rr < 3; rr++) {
        const int gy  = y + rr - 1;
        const bool rok = ((unsigned)gy < (unsigned)H_);
        const float* p = xb + gy * W_ + xx;
        v[rr][0] = (rok & pl) ? __ldg(p - 1) : 0.f;
        v[rr][1] = rok        ? __ldg(p)     : 0.f;
        v[rr][2] = rok        ? __ldg(p + 1) : 0.f;
        v[rr][3] = (rok & pr) ? __ldg(p + 2) : 0.f;
    }

    // Stable-descending ranks for both windows, accumulated directly from
    // signed masks (m = -1 when earlier-index element wins; ties -> earlier
    // index, matching stable jnp.argsort(-p)). Masks die immediately.
    int r0[9], r1[9];
#pragma unroll
    for (int e = 0; e < 9; e++) { r0[e] = 8 - e; r1[e] = 8 - e; }

    // within-row pairs (a<b), skip unused (0,3)
#pragma unroll
    for (int rr = 0; rr < 3; rr++) {
#pragma unroll
        for (int a = 0; a < 4; a++) {
#pragma unroll
            for (int b = a + 1; b < 4; b++) {
                if (a == 0 && b == 3) continue;
                const int m = setge(v[rr][a], v[rr][b]);
                if (b <= 2) { r0[rr*3 + a]     += m; r0[rr*3 + b]     -= m; }
                if (a >= 1) { r1[rr*3 + a - 1] += m; r1[rr*3 + b - 1] -= m; }
            }
        }
    }
    // cross-row pairs: row pairs (0,1),(0,2),(1,2), all col combos except (0,3),(3,0)
#pragma unroll
    for (int rp = 0; rp < 3; rp++) {
        const int ra = (rp < 2) ? 0 : 1;
        const int rb = (rp == 0) ? 1 : 2;
#pragma unroll
        for (int a = 0; a < 4; a++) {
#pragma unroll
            for (int b = 0; b < 4; b++) {
                if ((a == 0 && b == 3) || (a == 3 && b == 0)) continue;
                const int m = setge(v[ra][a], v[rb][b]);   // (ra,·) earlier index
                if (a <= 2 && b <= 2) { r0[ra*3 + a]     += m; r0[rb*3 + b]     -= m; }
                if (a >= 1 && b >= 1) { r1[ra*3 + a - 1] += m; r1[rb*3 + b - 1] -= m; }
            }
        }
    }

    // Values (gather s via conflict-free LDS) + index scatter into warp stage
    float acc0 = 0.f, acc1 = 0.f;
    float* st = &stage[warp][lane * 18];
#pragma unroll
    for (int e = 0; e < 9; e++) {
        acc0 = fmaf(v[e/3][e%3],     ssm[warp][r0[e]], acc0);
        acc1 = fmaf(v[e/3][e%3 + 1], ssm[warp][r1[e]], acc1);
        st[r0[e]]     = (float)e;    // constant payload, no I2F
        st[9 + r1[e]] = (float)e;
    }

    if (vout) {
        float2 o = make_float2(acc0, acc1);
        *(float2*)(vout + (size_t)bc * HW_ + y * W_ + xx) = o;   // 8B aligned (xx even)
    }

    __syncwarp();
    if (idxout) {
        // warp's 64 pixels own a contiguous 576-float (144 float4) span
        const float4* sf  = (const float4*)stage[warp];
        float4*       dst = (float4*)(idxout + (size_t)(t - lane) * 18);
#pragma unroll
        for (int k = 0; k < 4; k++)
            dst[lane + 32 * k] = sf[lane + 32 * k];
        if (lane < 16)
            dst[lane + 128] = sf[lane + 128];
    }
}

extern "C" void kernel_launch(void* const* d_in, const int* in_sizes, int n_in,
                              void* d_out, int out_size) {
    const float* x = (const float*)d_in[0];
    const float* s = (const float*)d_in[1];

    float* vout   = (float*)d_out;
    float* idxout = nullptr;

    // Reference returns (out[B,C,H,W], indices[B,C,H,W,9]); harness concatenates.
    if (out_size >= 10 * TOTAL_) {
        idxout = (float*)d_out + TOTAL_;   // [out | indices]
    } else if (out_size == 9 * TOTAL_) {
        idxout = (float*)d_out;            // indices only
        vout   = nullptr;
    }

    const int blocks = NPAIR_TOT / TPB;    // exact: 12544
    rrsvm_kernel<<<blocks, TPB>>>(x, s, vout, idxout);
}